// round 11
// baseline (speedup 1.0000x reference)
#include <cuda_runtime.h>
#include <cuda_fp16.h>
#include <math.h>
#include <stdint.h>

// ---------------- problem constants ----------------
#define B_ 4
#define T_ 4096
#define F_ 131           // 1 mean + 128 z + 1 v + 1 noise
#define D_ 128
#define TILE 128
#define NT 32            // T_/TILE
#define NPAIR 528        // NT*(NT+1)/2
#define JITTER_ 1e-6f

// per-row precomputed: w = exp(-sq/256)*v ; nsp = softplus(noise)
__device__ float g_w[B_ * T_];
__device__ float g_nsp[B_ * T_];

// ---------------- SMEM layout ----------------
// fp16 tiles: 128 rows x 136 halfs (272 B row stride)
#define TROW 136
#define TILE_BYTES (128 * TROW * 2)      // 34816
#define A_OFF 0
#define B_OFF TILE_BYTES
#define SMEM_BYTES (2 * TILE_BYTES)      // 69632
// stage (reuses tile region): 128 x 132 floats = 67584 B
#define SSTRIDE 132

__device__ __forceinline__ uint32_t smem_u32(const void* p) {
    uint32_t a;
    asm("{ .reg .u64 t; cvta.to.shared.u64 t, %1; cvt.u32.u64 %0, t; }"
        : "=r"(a) : "l"(p));
    return a;
}

#define LDMX4(r0, r1, r2, r3, addr)                                        \
    asm volatile("ldmatrix.sync.aligned.m8n8.x4.shared.b16 {%0,%1,%2,%3}, [%4];" \
                 : "=r"(r0), "=r"(r1), "=r"(r2), "=r"(r3) : "r"(addr))

#define MMA16816(c, a0, a1, a2, a3, b0, b1)                                \
    asm volatile(                                                          \
        "mma.sync.aligned.m16n8k16.row.col.f32.f16.f16.f32 "               \
        "{%0,%1,%2,%3}, {%4,%5,%6,%7}, {%8,%9}, {%0,%1,%2,%3};"            \
        : "+f"((c)[0]), "+f"((c)[1]), "+f"((c)[2]), "+f"((c)[3])           \
        : "r"(a0), "r"(a1), "r"(a2), "r"(a3), "r"(b0), "r"(b1))

__device__ __forceinline__ void stg_cs4(float* p, float4 v) {
    asm volatile("st.global.cs.v4.f32 [%0], {%1, %2, %3, %4};"
                 :: "l"(p), "f"(v.x), "f"(v.y), "f"(v.z), "f"(v.w) : "memory");
}

__device__ __forceinline__ float ex2f(float x) {
    float y;
    asm("ex2.approx.ftz.f32 %0, %1;" : "=f"(y) : "f"(x));
    return y;
}

__device__ __forceinline__ uint32_t pack_h2(float x0, float x1) {
    __half h0 = __float2half_rn(x0);
    __half h1 = __float2half_rn(x1);
    return (uint32_t)__half_as_ushort(h0) | ((uint32_t)__half_as_ushort(h1) << 16);
}

// ---------------- prologue ----------------
__global__ void __launch_bounds__(256) pre_kernel(const float* __restrict__ in,
                                                  float* __restrict__ mean_out) {
    int warp = (blockIdx.x * blockDim.x + threadIdx.x) >> 5;
    int lane = threadIdx.x & 31;
    if (warp >= B_ * T_) return;
    const float* row = in + (size_t)warp * F_;
    float s = 0.f;
#pragma unroll
    for (int k = 0; k < 4; k++) {
        float z = row[1 + lane + 32 * k];
        s += z * z;
    }
#pragma unroll
    for (int off = 16; off; off >>= 1) s += __shfl_xor_sync(0xffffffffu, s, off);
    if (lane == 0) {
        float v = row[1 + D_];
        float noise = row[F_ - 1];
        g_w[warp] = exp2f(-s * 0.0056355275034725f) * v;  // exp(-s/256)*v
        g_nsp[warp] = fmaxf(noise, 0.f) + log1pf(__expf(-fabsf(noise)));
        mean_out[warp] = row[0];
    }
}

// ---------------- main kernel ----------------
extern __shared__ char smem[];

__global__ void __launch_bounds__(256, 2) cov_kernel(const float* __restrict__ in,
                                                     float* __restrict__ fcov,
                                                     float* __restrict__ ycov) {
    const int b = blockIdx.y;
    int u = blockIdx.x;
    int ti = 0;
    while (u >= NT - ti) { u -= NT - ti; ti++; }
    const int tj = ti + u;
    const int i0 = ti * TILE, j0 = tj * TILE;
    const bool diag = (ti == tj);

    const int tid = threadIdx.x;
    const int wid = tid >> 5;
    const int lane = tid & 31;
    const uint32_t sb = smem_u32(smem);

    // ---- load + fp16 convert into SMEM ----
    const float* base = in + (size_t)b * T_ * F_;
#pragma unroll 4
    for (int it = 0; it < 32; it++) {
        int p = it * 256 + tid;          // 0..8191 (128 rows x 64 col-pairs)
        int r = p >> 6;
        int c2 = (p & 63) * 2;
        uint32_t soff = (uint32_t)(r * (TROW * 2) + c2 * 2);
        {
            const float* rp = base + (uint32_t)((i0 + r) * F_ + 1 + c2);
            *(uint32_t*)(smem + A_OFF + soff) = pack_h2(__ldg(rp), __ldg(rp + 1));
        }
        {
            const float* rp = base + (uint32_t)((j0 + r) * F_ + 1 + c2);
            *(uint32_t*)(smem + B_OFF + soff) = pack_h2(__ldg(rp), __ldg(rp + 1));
        }
    }
    __syncthreads();

    // ---- MMA: D = A . B^T (fp16 x fp16 -> fp32) ----
    const int m0 = (wid & 3) * 32;
    const int n0 = (wid >> 2) * 64;

    float acc[2][8][4];
#pragma unroll
    for (int a = 0; a < 2; a++)
#pragma unroll
        for (int n = 0; n < 8; n++)
#pragma unroll
            for (int q = 0; q < 4; q++) acc[a][n][q] = 0.f;

    const uint32_t aRowByte = (uint32_t)((m0 + (lane & 15)) * (TROW * 2) +
                                         ((lane >> 4) * 8) * 2);
    const uint32_t bRowByte =
        (uint32_t)((n0 + (lane & 7) + ((lane >> 4) << 3)) * (TROW * 2) +
                   (((lane >> 3) & 1) * 8) * 2);

#pragma unroll 1
    for (int ks = 0; ks < 8; ks++) {
        const uint32_t koff = (uint32_t)(ks * 32);
        uint32_t ra[2][4];
#pragma unroll
        for (int a = 0; a < 2; a++) {
            uint32_t addr = sb + A_OFF + aRowByte + a * 16 * (TROW * 2) + koff;
            LDMX4(ra[a][0], ra[a][1], ra[a][2], ra[a][3], addr);
        }
#pragma unroll
        for (int nt = 0; nt < 4; nt++) {
            uint32_t rb[4];
            uint32_t addr = sb + B_OFF + bRowByte + nt * 16 * (TROW * 2) + koff;
            LDMX4(rb[0], rb[1], rb[2], rb[3], addr);
#pragma unroll
            for (int a = 0; a < 2; a++) {
                MMA16816(acc[a][2 * nt], ra[a][0], ra[a][1], ra[a][2], ra[a][3],
                         rb[0], rb[1]);
                MMA16816(acc[a][2 * nt + 1], ra[a][0], ra[a][1], ra[a][2],
                         ra[a][3], rb[2], rb[3]);
            }
        }
    }
    __syncthreads();   // tiles consumed; stage region is free

    // ---- epilogue: f = exp2(g*SC)*wi*wj in-place, fill stage (normal) ----
    const int bT = b * T_;
    const float SC = 0.011271055006945f;  // log2(e)/128
    float* stage = (float*)smem;
    const uint32_t matBase = (uint32_t)b * (uint32_t)(T_ * T_);

    const int rA = lane >> 2;             // 0..7
    const int cQ = 2 * (lane & 3);        // 0,2,4,6

    {
        float wi[2][2], wj[8][2];
#pragma unroll
        for (int a = 0; a < 2; a++)
#pragma unroll
            for (int h = 0; h < 2; h++)
                wi[a][h] = __ldg(g_w + bT + i0 + m0 + a * 16 + rA + h * 8);
#pragma unroll
        for (int n = 0; n < 8; n++)
#pragma unroll
            for (int e = 0; e < 2; e++)
                wj[n][e] = __ldg(g_w + bT + j0 + n0 + n * 8 + cQ + e);

#pragma unroll
        for (int a = 0; a < 2; a++) {
#pragma unroll
            for (int n = 0; n < 8; n++) {
                const int r1 = m0 + a * 16 + rA;
                const int c = n0 + n * 8 + cQ;
#pragma unroll
                for (int q = 0; q < 4; q++)
                    acc[a][n][q] =
                        ex2f(acc[a][n][q] * SC) * wi[a][q >> 1] * wj[n][q & 1];
                // normal-orientation stage, STS.64 pairs
                *(float2*)(stage + r1 * SSTRIDE + c) =
                    make_float2(acc[a][n][0], acc[a][n][1]);
                *(float2*)(stage + (r1 + 8) * SSTRIDE + c) =
                    make_float2(acc[a][n][2], acc[a][n][3]);
            }
        }
    }
    __syncthreads();

    // ---- drain 1: direct tile, vector LDS.128 + STG.128 ----
#pragma unroll 2
    for (int it = 0; it < 16; it++) {
        int r = it * 8 + wid;
        float4 v = *(const float4*)(stage + r * SSTRIDE + 4 * lane);
        float4 y = v;
        if (diag && (r >> 2) == lane) {
            float nsp = __ldg(g_nsp + bT + i0 + r);
            int e = r & 3;
            (&v.x)[e] += JITTER_;
            (&y.x)[e] += JITTER_ + nsp;
        }
        uint32_t rowOff =
            matBase + (uint32_t)(i0 + r) * T_ + (uint32_t)(j0 + 4 * lane);
        stg_cs4(fcov + rowOff, v);
        stg_cs4(ycov + rowOff, y);
    }

    // ---- refill stage transposed + drain mirror (off-diagonal only) ----
    if (!diag) {
        __syncthreads();
#pragma unroll
        for (int a = 0; a < 2; a++) {
#pragma unroll
            for (int n = 0; n < 8; n++) {
                const int r1 = m0 + a * 16 + rA;
                const int c = n0 + n * 8 + cQ;
                stage[c * SSTRIDE + r1] = acc[a][n][0];
                stage[(c + 1) * SSTRIDE + r1] = acc[a][n][1];
                stage[c * SSTRIDE + r1 + 8] = acc[a][n][2];
                stage[(c + 1) * SSTRIDE + r1 + 8] = acc[a][n][3];
            }
        }
        __syncthreads();
#pragma unroll 2
        for (int it = 0; it < 16; it++) {
            int r = it * 8 + wid;   // mirror row (= original column)
            float4 v = *(const float4*)(stage + r * SSTRIDE + 4 * lane);
            uint32_t rowOff =
                matBase + (uint32_t)(j0 + r) * T_ + (uint32_t)(i0 + 4 * lane);
            stg_cs4(fcov + rowOff, v);
            stg_cs4(ycov + rowOff, v);
        }
    }
}

// ---------------- launch ----------------
extern "C" void kernel_launch(void* const* d_in, const int* in_sizes, int n_in,
                              void* d_out, int out_size) {
    const float* in = (const float*)d_in[0];
    float* out = (float*)d_out;
    float* mean = out;
    float* fcov = out + (size_t)B_ * T_;
    float* ycov = fcov + (size_t)B_ * T_ * T_;

    pre_kernel<<<(B_ * T_ * 32 + 255) / 256, 256>>>(in, mean);

    static int configured = 0;
    if (!configured) {
        cudaFuncSetAttribute(cov_kernel, cudaFuncAttributeMaxDynamicSharedMemorySize,
                             SMEM_BYTES);
        configured = 1;
    }
    dim3 grid(NPAIR, B_);
    cov_kernel<<<grid, 256, SMEM_BYTES>>>(in, fcov, ycov);
}

// round 16
// speedup vs baseline: 1.0307x; 1.0307x over previous
#include <cuda_runtime.h>
#include <cuda_fp16.h>
#include <math.h>
#include <stdint.h>

// ---------------- problem constants ----------------
#define B_ 4
#define T_ 4096
#define F_ 131           // 1 mean + 128 z + 1 v + 1 noise
#define D_ 128
#define TILE 128
#define NT 32            // T_/TILE
#define NPAIR 528        // NT*(NT+1)/2
#define JITTER_ 1e-6f

// per-row precomputed: w = exp(-sq/256)*v ; nsp = softplus(noise)
__device__ float g_w[B_ * T_];
__device__ float g_nsp[B_ * T_];

// ---------------- SMEM layout ----------------
// fp16 tiles: 128 rows x 136 halfs (272 B row stride); dead after MMA.
#define TROW 136
#define TILE_BYTES (128 * TROW * 2)      // 34816
#define A_OFF 0
#define B_OFF TILE_BYTES                 // tiles occupy [0, 69632)
// stage phase (after MMA): global transposed stage at 0 (128x132 f32 = 67584)
// + per-warp direct stage 16x68 f32 = 4352 B each at 67584 + wid*4352
#define SSTRIDE 132
#define GSTAGE_BYTES (128 * SSTRIDE * 4) // 67584
#define WSTAGE_OFF GSTAGE_BYTES
#define WSTAGE_BYTES 4352                // 16*68*4
#define SMEM_BYTES (WSTAGE_OFF + 8 * WSTAGE_BYTES)  // 102400

__device__ __forceinline__ uint32_t smem_u32(const void* p) {
    uint32_t a;
    asm("{ .reg .u64 t; cvta.to.shared.u64 t, %1; cvt.u32.u64 %0, t; }"
        : "=r"(a) : "l"(p));
    return a;
}

#define LDMX4(r0, r1, r2, r3, addr)                                        \
    asm volatile("ldmatrix.sync.aligned.m8n8.x4.shared.b16 {%0,%1,%2,%3}, [%4];" \
                 : "=r"(r0), "=r"(r1), "=r"(r2), "=r"(r3) : "r"(addr))

#define MMA16816(c, a0, a1, a2, a3, b0, b1)                                \
    asm volatile(                                                          \
        "mma.sync.aligned.m16n8k16.row.col.f32.f16.f16.f32 "               \
        "{%0,%1,%2,%3}, {%4,%5,%6,%7}, {%8,%9}, {%0,%1,%2,%3};"            \
        : "+f"((c)[0]), "+f"((c)[1]), "+f"((c)[2]), "+f"((c)[3])           \
        : "r"(a0), "r"(a1), "r"(a2), "r"(a3), "r"(b0), "r"(b1))

__device__ __forceinline__ void stg_cs4(float* p, float4 v) {
    asm volatile("st.global.cs.v4.f32 [%0], {%1, %2, %3, %4};"
                 :: "l"(p), "f"(v.x), "f"(v.y), "f"(v.z), "f"(v.w) : "memory");
}

__device__ __forceinline__ float ex2f(float x) {
    float y;
    asm("ex2.approx.ftz.f32 %0, %1;" : "=f"(y) : "f"(x));
    return y;
}

__device__ __forceinline__ uint32_t pack_h2(float x0, float x1) {
    __half h0 = __float2half_rn(x0);
    __half h1 = __float2half_rn(x1);
    return (uint32_t)__half_as_ushort(h0) | ((uint32_t)__half_as_ushort(h1) << 16);
}

// ---------------- prologue ----------------
__global__ void __launch_bounds__(256) pre_kernel(const float* __restrict__ in,
                                                  float* __restrict__ mean_out) {
    int warp = (blockIdx.x * blockDim.x + threadIdx.x) >> 5;
    int lane = threadIdx.x & 31;
    if (warp >= B_ * T_) return;
    const float* row = in + (size_t)warp * F_;
    float s = 0.f;
#pragma unroll
    for (int k = 0; k < 4; k++) {
        float z = row[1 + lane + 32 * k];
        s += z * z;
    }
#pragma unroll
    for (int off = 16; off; off >>= 1) s += __shfl_xor_sync(0xffffffffu, s, off);
    if (lane == 0) {
        float v = row[1 + D_];
        float noise = row[F_ - 1];
        g_w[warp] = exp2f(-s * 0.0056355275034725f) * v;  // exp(-s/256)*v
        g_nsp[warp] = fmaxf(noise, 0.f) + log1pf(__expf(-fabsf(noise)));
        mean_out[warp] = row[0];
    }
}

// ---------------- main kernel ----------------
extern __shared__ char smem[];

__global__ void __launch_bounds__(256, 2) cov_kernel(const float* __restrict__ in,
                                                     float* __restrict__ fcov,
                                                     float* __restrict__ ycov) {
    const int b = blockIdx.y;
    int u = blockIdx.x;
    int ti = 0;
    while (u >= NT - ti) { u -= NT - ti; ti++; }
    const int tj = ti + u;
    const int i0 = ti * TILE, j0 = tj * TILE;
    const bool diag = (ti == tj);

    const int tid = threadIdx.x;
    const int wid = tid >> 5;
    const int lane = tid & 31;
    const uint32_t sb = smem_u32(smem);

    // ---- load + fp16 convert into SMEM ----
    const float* base = in + (size_t)b * T_ * F_;
#pragma unroll 4
    for (int it = 0; it < 32; it++) {
        int p = it * 256 + tid;          // 0..8191 (128 rows x 64 col-pairs)
        int r = p >> 6;
        int c2 = (p & 63) * 2;
        uint32_t soff = (uint32_t)(r * (TROW * 2) + c2 * 2);
        {
            const float* rp = base + (uint32_t)((i0 + r) * F_ + 1 + c2);
            *(uint32_t*)(smem + A_OFF + soff) = pack_h2(__ldg(rp), __ldg(rp + 1));
        }
        {
            const float* rp = base + (uint32_t)((j0 + r) * F_ + 1 + c2);
            *(uint32_t*)(smem + B_OFF + soff) = pack_h2(__ldg(rp), __ldg(rp + 1));
        }
    }
    __syncthreads();

    // ---- MMA: D = A . B^T (fp16 x fp16 -> fp32) ----
    const int m0 = (wid & 3) * 32;
    const int n0 = (wid >> 2) * 64;

    float acc[2][8][4];
#pragma unroll
    for (int a = 0; a < 2; a++)
#pragma unroll
        for (int n = 0; n < 8; n++)
#pragma unroll
            for (int q = 0; q < 4; q++) acc[a][n][q] = 0.f;

    const uint32_t aRowByte = (uint32_t)((m0 + (lane & 15)) * (TROW * 2) +
                                         ((lane >> 4) * 8) * 2);
    const uint32_t bRowByte =
        (uint32_t)((n0 + (lane & 7) + ((lane >> 4) << 3)) * (TROW * 2) +
                   (((lane >> 3) & 1) * 8) * 2);

#pragma unroll 1
    for (int ks = 0; ks < 8; ks++) {
        const uint32_t koff = (uint32_t)(ks * 32);
        uint32_t ra[2][4];
#pragma unroll
        for (int a = 0; a < 2; a++) {
            uint32_t addr = sb + A_OFF + aRowByte + a * 16 * (TROW * 2) + koff;
            LDMX4(ra[a][0], ra[a][1], ra[a][2], ra[a][3], addr);
        }
#pragma unroll
        for (int nt = 0; nt < 4; nt++) {
            uint32_t rb[4];
            uint32_t addr = sb + B_OFF + bRowByte + nt * 16 * (TROW * 2) + koff;
            LDMX4(rb[0], rb[1], rb[2], rb[3], addr);
#pragma unroll
            for (int a = 0; a < 2; a++) {
                MMA16816(acc[a][2 * nt], ra[a][0], ra[a][1], ra[a][2], ra[a][3],
                         rb[0], rb[1]);
                MMA16816(acc[a][2 * nt + 1], ra[a][0], ra[a][1], ra[a][2],
                         ra[a][3], rb[2], rb[3]);
            }
        }
    }
    __syncthreads();   // tiles consumed; whole 102KB region is free

    // ---- epilogue + direct-tile store (per-warp staged, no CTA barrier) ----
    const int bT = b * T_;
    const float SC = 0.011271055006945f;  // log2(e)/128
    float* gstage = (float*)smem;                             // [128][132] transposed
    float* ws = (float*)(smem + WSTAGE_OFF + wid * WSTAGE_BYTES);  // [16][68]
    const uint32_t matBase = (uint32_t)b * (uint32_t)(T_ * T_);

    const int rA = lane >> 2;             // 0..7
    const int cQ = 2 * (lane & 3);        // 0,2,4,6

    float wi[2][2], wj[8][2];
#pragma unroll
    for (int a = 0; a < 2; a++)
#pragma unroll
        for (int h = 0; h < 2; h++)
            wi[a][h] = __ldg(g_w + bT + i0 + m0 + a * 16 + rA + h * 8);
#pragma unroll
    for (int n = 0; n < 8; n++)
#pragma unroll
        for (int e = 0; e < 2; e++)
            wj[n][e] = __ldg(g_w + bT + j0 + n0 + n * 8 + cQ + e);

#pragma unroll
    for (int a = 0; a < 2; a++) {
        // compute f for this 16-row half; stash mirror (transposed, ABSOLUTE col)
        // + direct (normal, warp-local col)
#pragma unroll
        for (int n = 0; n < 8; n++) {
            float f[4];
#pragma unroll
            for (int q = 0; q < 4; q++)
                f[q] = ex2f(acc[a][n][q] * SC) * wi[a][q >> 1] * wj[n][q & 1];

            const int cl = n * 8 + cQ;                 // warp-local col (even)
            if (!diag) {
                const int r1 = m0 + a * 16 + rA;       // tile-local row
                const int cg = n0 + cl;                // tile-absolute col
                gstage[cg * SSTRIDE + r1] = f[0];
                gstage[(cg + 1) * SSTRIDE + r1] = f[1];
                gstage[cg * SSTRIDE + r1 + 8] = f[2];
                gstage[(cg + 1) * SSTRIDE + r1 + 8] = f[3];
            }
            *(float2*)(ws + rA * 68 + cl) = make_float2(f[0], f[1]);
            *(float2*)(ws + (rA + 8) * 68 + cl) = make_float2(f[2], f[3]);
        }
        __syncwarp();
        // drain this 16-row half: LDS.128 + STG.128, rows contiguous
#pragma unroll
        for (int it = 0; it < 8; it++) {
            int rr = 2 * it + (lane >> 4);             // 0..15 within half
            int cl4 = 4 * (lane & 15);                 // 0..60
            float4 v = *(const float4*)(ws + rr * 68 + cl4);
            float4 y = v;
            if (diag) {
                int e = (m0 + a * 16 + rr) - (n0 + cl4);
                if (e >= 0 && e < 4) {
                    float nsp = __ldg(g_nsp + bT + i0 + m0 + a * 16 + rr);
                    (&v.x)[e] += JITTER_;
                    (&y.x)[e] += JITTER_ + nsp;
                }
            }
            uint32_t rowOff = matBase + (uint32_t)(i0 + m0 + a * 16 + rr) * T_ +
                              (uint32_t)(j0 + n0 + cl4);
            stg_cs4(fcov + rowOff, v);
            stg_cs4(ycov + rowOff, y);
        }
        __syncwarp();   // ws reused by next half
    }

    // ---- mirror tile (off-diagonal only): vector LDS.128 + STG.128 ----
    if (!diag) {
        __syncthreads();
#pragma unroll 2
        for (int it = 0; it < 16; it++) {
            int r = it * 8 + wid;   // mirror row (= original column)
            float4 v = *(const float4*)(gstage + r * SSTRIDE + 4 * lane);
            uint32_t rowOff =
                matBase + (uint32_t)(j0 + r) * T_ + (uint32_t)(i0 + 4 * lane);
            stg_cs4(fcov + rowOff, v);
            stg_cs4(ycov + rowOff, v);
        }
    }
}

// ---------------- launch ----------------
extern "C" void kernel_launch(void* const* d_in, const int* in_sizes, int n_in,
                              void* d_out, int out_size) {
    const float* in = (const float*)d_in[0];
    float* out = (float*)d_out;
    float* mean = out;
    float* fcov = out + (size_t)B_ * T_;
    float* ycov = fcov + (size_t)B_ * T_ * T_;

    pre_kernel<<<(B_ * T_ * 32 + 255) / 256, 256>>>(in, mean);

    static int configured = 0;
    if (!configured) {
        cudaFuncSetAttribute(cov_kernel, cudaFuncAttributeMaxDynamicSharedMemorySize,
                             SMEM_BYTES);
        configured = 1;
    }
    dim3 grid(NPAIR, B_);
    cov_kernel<<<grid, 256, SMEM_BYTES>>>(in, fcov, ycov);
}